// round 11
// baseline (speedup 1.0000x reference)
#include <cuda_runtime.h>
#include <cstdint>
#include <math.h>

#define T_MAX 1000
#define B_ 64
#define D_ 128
#define N_ 512
#define O_ 10

#define SIM_BLKS 64
#define TP_BLKS 256

__device__ float g_Iext[(size_t)T_MAX * B_ * N_];  // 131 MB scratch
__device__ float g_WT[N_ * N_];                    // W_rec transposed
__device__ unsigned g_cnt[512];                    // per-M-tile gemm completion (4 each)
__device__ unsigned g_tp;                          // transpose done counter
__device__ unsigned g_zf;                          // zfill (gemm-embedded) done counter

__global__ void reset_kernel() {
    int i = threadIdx.x;
    if (i < 512) g_cnt[i] = 0u;
    if (i == 0) { g_tp = 0u; g_zf = 0u; }
}

__device__ __forceinline__ unsigned ldacq(const unsigned* p) {
    unsigned v;
    asm volatile("ld.acquire.gpu.u32 %0, [%1];" : "=r"(v) : "l"(p));
    return v;
}

// warp0: spin until g_cnt[xbase .. xbase+nx-1] all >= 4 (x > xmax exempt)
__device__ __forceinline__ void verify_x(int tid, int xbase, int nx, int xmax) {
    if (tid < 32) {
        int x = xbase + tid;
        bool need = (tid < nx) && (x <= xmax);
        for (;;) {
            bool ok = !need || (ldacq(&g_cnt[x]) >= 4u);
            if (__ballot_sync(0xffffffffu, ok) == 0xffffffffu) break;
            __nanosleep(64);
        }
    }
}

__device__ __forceinline__ uint32_t f2tf32(float x) {
    uint32_t r;
    asm("cvt.rna.tf32.f32 %0, %1;" : "=r"(r) : "f"(x));
    return r;
}

__device__ __forceinline__ void mma_tf32(float& c0, float& c1, float& c2, float& c3,
                                         uint32_t a0, uint32_t a1, uint32_t a2, uint32_t a3,
                                         uint32_t b0, uint32_t b1) {
    asm volatile(
        "mma.sync.aligned.m16n8k8.row.col.f32.tf32.tf32.f32 "
        "{%0,%1,%2,%3}, {%4,%5,%6,%7}, {%8,%9}, {%0,%1,%2,%3};"
        : "+f"(c0), "+f"(c1), "+f"(c2), "+f"(c3)
        : "r"(a0), "r"(a1), "r"(a2), "r"(a3), "r"(b0), "r"(b1));
}

// ---------------- GEMM tile geometry (split-K: 64 cols per phase) ----------------
#define TLD 68                        // fp32 row pitch for 64-col phase (pad 4)
#define GEMM_DSMEM (2 * 128 * TLD * 4)   // 69632 B -> 2 CTAs/SM, co-resides with sim

__global__ __launch_bounds__(256) void mega(
    const float* __restrict__ X, const float* __restrict__ Win,
    const float* __restrict__ sc_p, const float* __restrict__ Wrec,
    const float* __restrict__ Wout, const float* __restrict__ bout,
    const float* __restrict__ osc_p,
    float* __restrict__ out, float* __restrict__ spk, float* __restrict__ vlt,
    float* __restrict__ pscO, float* __restrict__ filt,
    int T, int startT, int writeHist,
    float e_syn, float e_asc, float alpha)
{
    const int bid = blockIdx.x;
    const int tid = threadIdx.x;
    const size_t TBN = (size_t)T * B_ * N_;
    const int BN = B_ * N_;
    const int NG = (T / 2) * 4;   // gemm CTAs (M-tiles x 4 N-tiles)

    // ================= GEMM role (mma.sync tf32, split-K) + embedded zfill =================
    if (bid >= SIM_BLKS && bid < SIM_BLKS + NG) {
        extern __shared__ float sm[];
        uint32_t* As = (uint32_t*)sm;                 // [128][TLD] tf32 bits (64 k-cols)
        uint32_t* Bs = (uint32_t*)(sm + 128 * TLD);   // [128][TLD] tf32 bits (n-major)

        const int idg = bid - SIM_BLKS;
        const int x = idg >> 2;
        const int y = idg & 3;
        const int m0 = x * 128;
        const int n0 = y * 128;
        const int wrp = tid >> 5, lane = tid & 31;

        const float sc = __ldg(sc_p);

        // warp tile: 32(M) x 64(N).  mw = wrp&3 (M group), nw = wrp>>2 (N group)
        const int mw = (wrp & 3) * 32;
        const int nw = (wrp >> 2) * 64;
        const int lr = lane >> 2;     // 0..7
        const int lc = lane & 3;      // 0..3

        float c[2][8][4];
#pragma unroll
        for (int i = 0; i < 2; ++i)
#pragma unroll
            for (int j = 0; j < 8; ++j)
#pragma unroll
                for (int q = 0; q < 4; ++q) c[i][j][q] = 0.f;

#pragma unroll 1
        for (int kb = 0; kb < 2; ++kb) {
            if (kb) __syncthreads();
            // fill A and B phase tiles (128 rows x 64 cols), tf32-rounded at fill
#pragma unroll
            for (int p = 0; p < 8; ++p) {
                int id = tid + p * 256;           // 0..2047
                int m = id >> 4;                  // 0..127
                int c4 = (id & 15) * 4;           // 0..60
                float4 xv = *(const float4*)(X + (size_t)(m0 + m) * D_ + kb * 64 + c4);
                uint32_t* ar = As + m * TLD + c4;
                ar[0] = f2tf32(xv.x * sc); ar[1] = f2tf32(xv.y * sc);
                ar[2] = f2tf32(xv.z * sc); ar[3] = f2tf32(xv.w * sc);
                float4 wv = *(const float4*)(Win + (size_t)(n0 + m) * D_ + kb * 64 + c4);
                uint32_t* br = Bs + m * TLD + c4;
                br[0] = f2tf32(wv.x); br[1] = f2tf32(wv.y);
                br[2] = f2tf32(wv.z); br[3] = f2tf32(wv.w);
            }
            __syncthreads();

#pragma unroll 1
            for (int kk = 0; kk < 8; ++kk) {
                const int k0 = kk * 8;
                uint32_t a[2][4];
#pragma unroll
                for (int i = 0; i < 2; ++i) {
                    const uint32_t* ap = As + (mw + i * 16 + lr) * TLD + k0 + lc;
                    a[i][0] = ap[0];
                    a[i][1] = ap[8 * TLD];
                    a[i][2] = ap[4];
                    a[i][3] = ap[8 * TLD + 4];
                }
                uint32_t b[8][2];
#pragma unroll
                for (int j = 0; j < 8; ++j) {
                    const uint32_t* bp = Bs + (nw + j * 8 + lr) * TLD + k0 + lc;
                    b[j][0] = bp[0];
                    b[j][1] = bp[4];
                }
#pragma unroll
                for (int i = 0; i < 2; ++i)
#pragma unroll
                    for (int j = 0; j < 8; ++j)
                        mma_tf32(c[i][j][0], c[i][j][1], c[i][j][2], c[i][j][3],
                                 a[i][0], a[i][1], a[i][2], a[i][3], b[j][0], b[j][1]);
            }
        }

        // store C -> g_Iext
#pragma unroll
        for (int i = 0; i < 2; ++i) {
            const int r0 = m0 + mw + i * 16 + lr;
#pragma unroll
            for (int j = 0; j < 8; ++j) {
                const int col = n0 + nw + j * 8 + lc * 2;
                *(float2*)(g_Iext + (size_t)r0 * N_ + col) = make_float2(c[i][j][0], c[i][j][1]);
                *(float2*)(g_Iext + (size_t)(r0 + 8) * N_ + col) = make_float2(c[i][j][2], c[i][j][3]);
            }
        }
        // publish tile IMMEDIATELY (sim is waiting on g_cnt), zfill after
        __threadfence();
        __syncthreads();
        if (tid == 0) atomicAdd(&g_cnt[x], 1u);

        // ---- embedded zfill slice (off the tile critical path) ----
        if (writeHist) {
            const size_t na = TBN >> 2;              // spk float4s
            const size_t zt = na * 3;                // spk + (psc,filt contiguous)
            size_t per = (zt + (size_t)NG - 1) / (size_t)NG;
            size_t s0 = (size_t)idg * per;
            size_t s1 = s0 + per; if (s1 > zt) s1 = zt;
            float4 z = make_float4(0.f, 0.f, 0.f, 0.f);
            for (size_t i = s0 + tid; i < s1; i += 256) {
                if (i < na) ((float4*)spk)[i] = z;
                else        ((float4*)pscO)[i - na] = z;
            }
        }
        __threadfence();
        __syncthreads();
        if (tid == 0) atomicAdd(&g_zf, 1u);
        return;
    }

    // ================= transpose role (needed only on spikes) =================
    if (bid >= SIM_BLKS + NG) {
        __shared__ float tile[32][33];
        const int id2 = bid - SIM_BLKS - NG;
        const int bx = (id2 & 15) * 32, by = (id2 >> 4) * 32;
        const int tx = tid & 31, ty = tid >> 5;  // 32 x 8
#pragma unroll
        for (int i = 0; i < 32; i += 8)
            tile[ty + i][tx] = Wrec[(size_t)(by + ty + i) * N_ + (bx + tx)];
        __syncthreads();
#pragma unroll
        for (int i = 0; i < 32; i += 8)
            g_WT[(size_t)(bx + ty + i) * N_ + (by + tx)] = tile[tx][ty + i];
        __threadfence();
        __syncthreads();
        if (tid == 0) atomicAdd(&g_tp, 1u);
        return;
    }

    // ===== sim role: 1 CTA/batch, 256 thr, 2 neurons/thread =====
    {
        const int b = blockIdx.x;
        const int lane = tid & 31, wid = tid >> 5;
        const int n0 = tid * 2;
        const int mword = tid >> 4;
        const int mbit0 = (tid & 15) * 2;
        const int xmax = ((T - 1) >> 1);

        __shared__ unsigned smask[2][16];
        __shared__ float sred[8];
        __shared__ int s_ever;
        if (tid < 16) { smask[0][tid] = 0u; smask[1][tid] = 0u; }
        if (tid == 0) s_ever = 0;

        verify_x(tid, 0, 8, xmax);    // tiles 0..7 = times 0..15 (ring + first block loads)
        __syncthreads();

        const float a_mem = 0.05f, VR = -60.0f, VTH = -45.0f, KP = 0.2f, AA = -0.2f;
        const float oma = 1.0f - alpha;
        float v[2], asc[2], rr[2], psc[2], f[2], fsum[2];
        int rcnt[2];
#pragma unroll
        for (int k = 0; k < 2; ++k) {
            v[k] = VR; asc[k] = 0.f; rr[k] = 0.f; psc[k] = 0.f;
            f[k] = 0.f; fsum[k] = 0.f; rcnt[k] = 0;
        }
        const float* Ibase = g_Iext + (size_t)b * N_ + n0;

        float2 pre[8];
#pragma unroll
        for (int j = 0; j < 8; ++j) {
            if (j < T) pre[j] = *(const float2*)(Ibase + (size_t)j * BN);
            else       pre[j] = make_float2(0.f, 0.f);
        }

        int rb = 0, prev_any = 0;
        const int Tm = T & ~7;
        for (int t0 = 0; t0 < Tm; t0 += 8) {
            // verify tiles consumed by NEXT block's prefetches
            verify_x(tid, (t0 >> 1) + 8, 4, xmax);
#pragma unroll
            for (int j = 0; j < 8; ++j) {
                const int tt = t0 + j;
                const float2 It2 = pre[j];
                if (tt + 8 < T) pre[j] = *(const float2*)(Ibase + (size_t)(tt + 8) * BN);

                float rec[2] = {0.f, 0.f};
                if (prev_any) {
#pragma unroll 1
                    for (int w = 0; w < 16; ++w) {
                        unsigned m = smask[rb][w];
                        while (m) {
                            int bit = __ffs((int)m) - 1;
                            m &= (m - 1);
                            float2 wv = *(const float2*)(g_WT + ((size_t)(w * 32 + bit) << 9) + n0);
                            rec[0] += wv.x; rec[1] += wv.y;
                        }
                    }
                }

                const float Iin[2] = {It2.x, It2.y};
                float s[2];
                int spiked = 0;
#pragma unroll
                for (int k = 0; k < 2; ++k) {
                    rr[k] = rr[k] * e_syn + rec[k];
                    psc[k] = psc[k] * e_syn + KP * rr[k];
                    v[k] = v[k] + a_mem * (VR - v[k]) + a_mem * (Iin[k] + psc[k] + asc[k]);
                    bool inref = rcnt[k] > 0;
                    if (inref) v[k] = VR;
                    s[k] = (v[k] - VTH >= 0.0f) ? 1.0f : 0.0f;
                    if (s[k] > 0.0f) { v[k] = VR; rcnt[k] = 5; spiked = 1; }
                    else             { rcnt[k] = inref ? rcnt[k] - 1 : 0; }
                    asc[k] = asc[k] * e_asc + AA * s[k];
                    f[k] = (tt == 0) ? s[k] : (alpha * f[k] + oma * s[k]);
                    if (tt >= startT) fsum[k] += f[k];
                }
                int any = __syncthreads_or(spiked);
                int ever = s_ever;
                if (any && !ever) {
                    if (tid == 0) {
                        while (ldacq(&g_tp) < (unsigned)TP_BLKS) __nanosleep(64);
                        if (writeHist)
                            while (ldacq(&g_zf) < (unsigned)NG) __nanosleep(64);
                        s_ever = 1;
                    }
                    __syncthreads();
                    ever = 1;
                }
                if (writeHist) {
                    size_t idx = (size_t)tt * BN + (size_t)b * N_ + n0;
                    *(float2*)(vlt + idx) = make_float2(v[0], v[1]);
                    if (ever) {
#pragma unroll
                        for (int k = 0; k < 2; ++k) {
                            if (s[k] != 0.0f)   spk[idx + k] = s[k];
                            if (psc[k] != 0.0f) pscO[idx + k] = psc[k];
                            if (f[k] != 0.0f)   filt[idx + k] = f[k];
                        }
                    }
                }
                if (any | prev_any) {
                    const int wb = rb ^ 1;
                    if (prev_any && tid < 16) smask[rb][tid] = 0u;
                    if (spiked) {
                        unsigned bits = 0u;
#pragma unroll
                        for (int k = 0; k < 2; ++k)
                            if (s[k] != 0.0f) bits |= 1u << (mbit0 + k);
                        atomicOr(&smask[wb][mword], bits);
                    }
                    __syncthreads();
                    if (any) rb = wb;
                }
                prev_any = any;
            }
        }

        // remainder steps (T % 8)
        if (Tm < T) {
            if (tid == 0)
                for (int x = (Tm >> 1); x <= xmax; ++x)
                    while (ldacq(&g_cnt[x]) < 4u) __nanosleep(64);
            __syncthreads();
            for (int tt = Tm; tt < T; ++tt) {
                const float2 It2 = *(const float2*)(Ibase + (size_t)tt * BN);
                float rec[2] = {0.f, 0.f};
                if (prev_any) {
#pragma unroll 1
                    for (int w = 0; w < 16; ++w) {
                        unsigned m = smask[rb][w];
                        while (m) {
                            int bit = __ffs((int)m) - 1;
                            m &= (m - 1);
                            float2 wv = *(const float2*)(g_WT + ((size_t)(w * 32 + bit) << 9) + n0);
                            rec[0] += wv.x; rec[1] += wv.y;
                        }
                    }
                }
                const float Iin[2] = {It2.x, It2.y};
                float s[2];
                int spiked = 0;
#pragma unroll
                for (int k = 0; k < 2; ++k) {
                    rr[k] = rr[k] * e_syn + rec[k];
                    psc[k] = psc[k] * e_syn + KP * rr[k];
                    v[k] = v[k] + a_mem * (VR - v[k]) + a_mem * (Iin[k] + psc[k] + asc[k]);
                    bool inref = rcnt[k] > 0;
                    if (inref) v[k] = VR;
                    s[k] = (v[k] - VTH >= 0.0f) ? 1.0f : 0.0f;
                    if (s[k] > 0.0f) { v[k] = VR; rcnt[k] = 5; spiked = 1; }
                    else             { rcnt[k] = inref ? rcnt[k] - 1 : 0; }
                    asc[k] = asc[k] * e_asc + AA * s[k];
                    f[k] = (tt == 0) ? s[k] : (alpha * f[k] + oma * s[k]);
                    if (tt >= startT) fsum[k] += f[k];
                }
                int any = __syncthreads_or(spiked);
                int ever = s_ever;
                if (any && !ever) {
                    if (tid == 0) {
                        while (ldacq(&g_tp) < (unsigned)TP_BLKS) __nanosleep(64);
                        if (writeHist)
                            while (ldacq(&g_zf) < (unsigned)NG) __nanosleep(64);
                        s_ever = 1;
                    }
                    __syncthreads();
                    ever = 1;
                }
                if (writeHist) {
                    size_t idx = (size_t)tt * BN + (size_t)b * N_ + n0;
                    *(float2*)(vlt + idx) = make_float2(v[0], v[1]);
                    if (ever) {
#pragma unroll
                        for (int k = 0; k < 2; ++k) {
                            if (s[k] != 0.0f)   spk[idx + k] = s[k];
                            if (psc[k] != 0.0f) pscO[idx + k] = psc[k];
                            if (f[k] != 0.0f)   filt[idx + k] = f[k];
                        }
                    }
                }
                if (any | prev_any) {
                    const int wb = rb ^ 1;
                    if (prev_any && tid < 16) smask[rb][tid] = 0u;
                    if (spiked) {
                        unsigned bits = 0u;
#pragma unroll
                        for (int k = 0; k < 2; ++k)
                            if (s[k] != 0.0f) bits |= 1u << (mbit0 + k);
                        atomicOr(&smask[wb][mword], bits);
                    }
                    __syncthreads();
                    if (any) rb = wb;
                }
                prev_any = any;
            }
        }

        // readout
        const float cnt = (float)(T - startT);
        const float osc = __ldg(osc_p);
        float a0 = (fsum[0] / cnt) * osc;
        float a1 = (fsum[1] / cnt) * osc;
#pragma unroll 1
        for (int o = 0; o < O_; ++o) {
            float2 w2 = *(const float2*)(Wout + (size_t)o * N_ + n0);
            float val = a0 * w2.x + a1 * w2.y;
#pragma unroll
            for (int off = 16; off > 0; off >>= 1)
                val += __shfl_down_sync(0xffffffffu, val, off);
            if (lane == 0) sred[wid] = val;
            __syncthreads();
            if (tid == 0) {
                float acc = __ldg(bout + o);
#pragma unroll
                for (int q = 0; q < 8; ++q) acc += sred[q];
                out[b * O_ + o] = acc;
            }
            __syncthreads();
        }
    }
}

extern "C" void kernel_launch(void* const* d_in, const int* in_sizes, int n_in,
                              void* d_out, int out_size) {
    const float* x    = (const float*)d_in[0];
    const float* Win  = (const float*)d_in[1];
    const float* isc  = (const float*)d_in[2];
    const float* Wrec = (const float*)d_in[3];
    const float* Wout = (const float*)d_in[4];
    const float* bout = (const float*)d_in[5];
    const float* osc  = (const float*)d_in[6];

    const int T = in_sizes[0] / (B_ * D_);
    float* out = (float*)d_out;
    const size_t TBN = (size_t)T * B_ * N_;
    const long long fullsz = (long long)B_ * O_ + 4LL * (long long)TBN;
    const int writeHist = ((long long)out_size >= fullsz) ? 1 : 0;
    float* spk = out + B_ * O_;
    float* vlt = spk + TBN;
    float* psc = vlt + TBN;
    float* flt = psc + TBN;

    const float e_syn = (float)exp((double)(-1.0f / 5.0f));
    const float e_asc = (float)exp((double)(-1.0f / 700.0f));
    const float alpha = (float)exp((double)(-1.0f / 20.0f));
    // int(T * (1.0 - 0.8)) truncates (float artifact): 199 for T=1000
    const int startT = (int)((double)T * (1.0 - 0.8));

    const int NG = (T / 2) * 4;                 // gemm CTAs (M-tiles x 4 N-tiles)
    const int grid = SIM_BLKS + NG + TP_BLKS;   // sim | gemm | transpose

    reset_kernel<<<1, 512>>>();

    cudaFuncSetAttribute(mega, cudaFuncAttributeMaxDynamicSharedMemorySize, GEMM_DSMEM);
    mega<<<grid, 256, GEMM_DSMEM>>>(x, Win, isc, Wrec, Wout, bout, osc,
                                    out, spk, vlt, psc, flt,
                                    T, startT, writeHist, e_syn, e_asc, alpha);
}

// round 12
// speedup vs baseline: 1.1558x; 1.1558x over previous
#include <cuda_runtime.h>
#include <cstdint>
#include <math.h>

#define T_MAX 1000
#define B_ 64
#define D_ 128
#define N_ 512
#define O_ 10

#define SIM_BLKS 64
#define TP_BLKS 256

__device__ float g_Iext[(size_t)T_MAX * B_ * N_];  // 131 MB scratch
__device__ float g_WT[N_ * N_];                    // W_rec transposed
__device__ unsigned g_cnt[512];                    // per-M-tile gemm completion (4 each)
__device__ unsigned g_tp;                          // transpose done counter

__global__ void reset_kernel() {
    int i = threadIdx.x;
    if (i < 512) g_cnt[i] = 0u;
    if (i == 0) g_tp = 0u;
}

__device__ __forceinline__ unsigned ldacq(const unsigned* p) {
    unsigned v;
    asm volatile("ld.acquire.gpu.u32 %0, [%1];" : "=r"(v) : "l"(p));
    return v;
}

// warp0: spin until g_cnt[xbase .. xbase+nx-1] all >= 4 (x > xmax exempt)
__device__ __forceinline__ void verify_x(int tid, int xbase, int nx, int xmax) {
    if (tid < 32) {
        int x = xbase + tid;
        bool need = (tid < nx) && (x <= xmax);
        for (;;) {
            bool ok = !need || (ldacq(&g_cnt[x]) >= 4u);
            if (__ballot_sync(0xffffffffu, ok) == 0xffffffffu) break;
            __nanosleep(64);
        }
    }
}

__device__ __forceinline__ uint32_t f2tf32(float x) {
    uint32_t r;
    asm("cvt.rna.tf32.f32 %0, %1;" : "=r"(r) : "f"(x));
    return r;
}

__device__ __forceinline__ void mma_tf32(float& c0, float& c1, float& c2, float& c3,
                                         uint32_t a0, uint32_t a1, uint32_t a2, uint32_t a3,
                                         uint32_t b0, uint32_t b1) {
    asm volatile(
        "mma.sync.aligned.m16n8k8.row.col.f32.tf32.tf32.f32 "
        "{%0,%1,%2,%3}, {%4,%5,%6,%7}, {%8,%9}, {%0,%1,%2,%3};"
        : "+f"(c0), "+f"(c1), "+f"(c2), "+f"(c3)
        : "r"(a0), "r"(a1), "r"(a2), "r"(a3), "r"(b0), "r"(b1));
}

// ---------------- GEMM tile geometry (full-K, round-9 config) ----------------
#define TLD 132                       // fp32 row pitch (pad 4)
#define GEMM_DSMEM (2 * 128 * TLD * 4)

__global__ __launch_bounds__(256) void mega(
    const float* __restrict__ X, const float* __restrict__ Win,
    const float* __restrict__ sc_p, const float* __restrict__ Wrec,
    const float* __restrict__ Wout, const float* __restrict__ bout,
    const float* __restrict__ osc_p,
    float* __restrict__ out, float* __restrict__ spk, float* __restrict__ vlt,
    float* __restrict__ pscO, float* __restrict__ filt,
    int T, int startT, int writeHist,
    float e_syn, float e_asc, float alpha)
{
    const int bid = blockIdx.x;
    const int tid = threadIdx.x;
    const int BN = B_ * N_;
    const int NG = (T / 2) * 4;   // gemm CTAs (M-tiles x 4 N-tiles)

    // ================= GEMM role (mma.sync tf32, full-K) =================
    if (bid >= SIM_BLKS && bid < SIM_BLKS + NG) {
        extern __shared__ float sm[];
        uint32_t* As = (uint32_t*)sm;                 // [128][TLD] tf32 bits
        uint32_t* Bs = (uint32_t*)(sm + 128 * TLD);   // [128][TLD] tf32 bits (n-major)

        const int idg = bid - SIM_BLKS;
        const int x = idg >> 2;
        const int y = idg & 3;
        const int m0 = x * 128;
        const int n0 = y * 128;
        const int wrp = tid >> 5, lane = tid & 31;

        const float sc = __ldg(sc_p);
#pragma unroll
        for (int p = 0; p < 16; ++p) {
            int id = tid + p * 256;           // 0..4095
            int m = id >> 5;
            int c4 = (id & 31) * 4;
            float4 xv = *(const float4*)(X + (size_t)(m0 + m) * D_ + c4);
            uint32_t* ar = As + m * TLD + c4;
            ar[0] = f2tf32(xv.x * sc); ar[1] = f2tf32(xv.y * sc);
            ar[2] = f2tf32(xv.z * sc); ar[3] = f2tf32(xv.w * sc);
            float4 wv = *(const float4*)(Win + (size_t)(n0 + m) * D_ + c4);
            uint32_t* br = Bs + m * TLD + c4;
            br[0] = f2tf32(wv.x); br[1] = f2tf32(wv.y);
            br[2] = f2tf32(wv.z); br[3] = f2tf32(wv.w);
        }
        __syncthreads();

        // warp tile: 32(M) x 64(N)
        const int mw = (wrp & 3) * 32;
        const int nw = (wrp >> 2) * 64;
        const int lr = lane >> 2;     // 0..7
        const int lc = lane & 3;      // 0..3

        float c[2][8][4];
#pragma unroll
        for (int i = 0; i < 2; ++i)
#pragma unroll
            for (int j = 0; j < 8; ++j)
#pragma unroll
                for (int q = 0; q < 4; ++q) c[i][j][q] = 0.f;

#pragma unroll 1
        for (int kk = 0; kk < 16; ++kk) {
            const int k0 = kk * 8;
            uint32_t a[2][4];
#pragma unroll
            for (int i = 0; i < 2; ++i) {
                const uint32_t* ap = As + (mw + i * 16 + lr) * TLD + k0 + lc;
                a[i][0] = ap[0];
                a[i][1] = ap[8 * TLD];
                a[i][2] = ap[4];
                a[i][3] = ap[8 * TLD + 4];
            }
            uint32_t b[8][2];
#pragma unroll
            for (int j = 0; j < 8; ++j) {
                const uint32_t* bp = Bs + (nw + j * 8 + lr) * TLD + k0 + lc;
                b[j][0] = bp[0];
                b[j][1] = bp[4];
            }
#pragma unroll
            for (int i = 0; i < 2; ++i)
#pragma unroll
                for (int j = 0; j < 8; ++j)
                    mma_tf32(c[i][j][0], c[i][j][1], c[i][j][2], c[i][j][3],
                             a[i][0], a[i][1], a[i][2], a[i][3], b[j][0], b[j][1]);
        }

        // store C -> g_Iext, publish immediately
#pragma unroll
        for (int i = 0; i < 2; ++i) {
            const int r0 = m0 + mw + i * 16 + lr;
#pragma unroll
            for (int j = 0; j < 8; ++j) {
                const int col = n0 + nw + j * 8 + lc * 2;
                *(float2*)(g_Iext + (size_t)r0 * N_ + col) = make_float2(c[i][j][0], c[i][j][1]);
                *(float2*)(g_Iext + (size_t)(r0 + 8) * N_ + col) = make_float2(c[i][j][2], c[i][j][3]);
            }
        }
        __threadfence();
        __syncthreads();
        if (tid == 0) atomicAdd(&g_cnt[x], 1u);
        return;
    }

    // ================= transpose role (needed only on spikes) =================
    if (bid >= SIM_BLKS + NG) {
        __shared__ float tile[32][33];
        const int id2 = bid - SIM_BLKS - NG;
        const int bx = (id2 & 15) * 32, by = (id2 >> 4) * 32;
        const int tx = tid & 31, ty = tid >> 5;  // 32 x 8
#pragma unroll
        for (int i = 0; i < 32; i += 8)
            tile[ty + i][tx] = Wrec[(size_t)(by + ty + i) * N_ + (bx + tx)];
        __syncthreads();
#pragma unroll
        for (int i = 0; i < 32; i += 8)
            g_WT[(size_t)(bx + ty + i) * N_ + (by + tx)] = tile[tx][ty + i];
        __threadfence();
        __syncthreads();
        if (tid == 0) atomicAdd(&g_tp, 1u);
        return;
    }

    // ===== sim role: 1 CTA/batch, 256 thr, 2 neurons/thread; writes all 4 arrays =====
    {
        const int b = blockIdx.x;
        const int lane = tid & 31, wid = tid >> 5;
        const int n0 = tid * 2;
        const int mword = tid >> 4;
        const int mbit0 = (tid & 15) * 2;
        const int xmax = ((T - 1) >> 1);

        __shared__ unsigned smask[2][16];
        __shared__ float sred[8];
        __shared__ int s_ever;
        if (tid < 16) { smask[0][tid] = 0u; smask[1][tid] = 0u; }
        if (tid == 0) s_ever = 0;

        verify_x(tid, 0, 8, xmax);    // tiles 0..7 = times 0..15 (ring + first block loads)
        __syncthreads();

        const float a_mem = 0.05f, VR = -60.0f, VTH = -45.0f, KP = 0.2f, AA = -0.2f;
        const float oma = 1.0f - alpha;
        float v[2], asc[2], rr[2], psc[2], f[2], fsum[2];
        int rcnt[2];
#pragma unroll
        for (int k = 0; k < 2; ++k) {
            v[k] = VR; asc[k] = 0.f; rr[k] = 0.f; psc[k] = 0.f;
            f[k] = 0.f; fsum[k] = 0.f; rcnt[k] = 0;
        }
        const float* Ibase = g_Iext + (size_t)b * N_ + n0;

        float2 pre[8];
#pragma unroll
        for (int j = 0; j < 8; ++j) {
            if (j < T) pre[j] = *(const float2*)(Ibase + (size_t)j * BN);
            else       pre[j] = make_float2(0.f, 0.f);
        }

        int rb = 0, prev_any = 0;
        const int Tm = T & ~7;
        for (int t0 = 0; t0 < Tm; t0 += 8) {
            // verify tiles consumed by NEXT block's prefetches
            verify_x(tid, (t0 >> 1) + 8, 4, xmax);
#pragma unroll
            for (int j = 0; j < 8; ++j) {
                const int tt = t0 + j;
                const float2 It2 = pre[j];
                if (tt + 8 < T) pre[j] = *(const float2*)(Ibase + (size_t)(tt + 8) * BN);

                float rec[2] = {0.f, 0.f};
                if (prev_any) {
#pragma unroll 1
                    for (int w = 0; w < 16; ++w) {
                        unsigned m = smask[rb][w];
                        while (m) {
                            int bit = __ffs((int)m) - 1;
                            m &= (m - 1);
                            float2 wv = *(const float2*)(g_WT + ((size_t)(w * 32 + bit) << 9) + n0);
                            rec[0] += wv.x; rec[1] += wv.y;
                        }
                    }
                }

                const float Iin[2] = {It2.x, It2.y};
                float s[2];
                int spiked = 0;
#pragma unroll
                for (int k = 0; k < 2; ++k) {
                    rr[k] = rr[k] * e_syn + rec[k];
                    psc[k] = psc[k] * e_syn + KP * rr[k];
                    v[k] = v[k] + a_mem * (VR - v[k]) + a_mem * (Iin[k] + psc[k] + asc[k]);
                    bool inref = rcnt[k] > 0;
                    if (inref) v[k] = VR;
                    s[k] = (v[k] - VTH >= 0.0f) ? 1.0f : 0.0f;
                    if (s[k] > 0.0f) { v[k] = VR; rcnt[k] = 5; spiked = 1; }
                    else             { rcnt[k] = inref ? rcnt[k] - 1 : 0; }
                    asc[k] = asc[k] * e_asc + AA * s[k];
                    f[k] = (tt == 0) ? s[k] : (alpha * f[k] + oma * s[k]);
                    if (tt >= startT) fsum[k] += f[k];
                }

                if (writeHist) {
                    size_t idx = (size_t)tt * BN + (size_t)b * N_ + n0;
                    *(float2*)(vlt + idx)  = make_float2(v[0], v[1]);
                    *(float2*)(spk + idx)  = make_float2(s[0], s[1]);
                    *(float2*)(pscO + idx) = make_float2(psc[0], psc[1]);
                    *(float2*)(filt + idx) = make_float2(f[0], f[1]);
                }

                int any = __syncthreads_or(spiked);
                if (any && !s_ever) {
                    // first spike: wait for g_WT (transpose blocks) once
                    if (tid == 0) {
                        while (ldacq(&g_tp) < (unsigned)TP_BLKS) __nanosleep(64);
                        s_ever = 1;
                    }
                    __syncthreads();
                }
                if (any | prev_any) {
                    const int wb = rb ^ 1;
                    if (prev_any && tid < 16) smask[rb][tid] = 0u;
                    if (spiked) {
                        unsigned bits = 0u;
#pragma unroll
                        for (int k = 0; k < 2; ++k)
                            if (s[k] != 0.0f) bits |= 1u << (mbit0 + k);
                        atomicOr(&smask[wb][mword], bits);
                    }
                    __syncthreads();
                    if (any) rb = wb;
                }
                prev_any = any;
            }
        }

        // remainder steps (T % 8)
        if (Tm < T) {
            if (tid == 0)
                for (int x = (Tm >> 1); x <= xmax; ++x)
                    while (ldacq(&g_cnt[x]) < 4u) __nanosleep(64);
            __syncthreads();
            for (int tt = Tm; tt < T; ++tt) {
                const float2 It2 = *(const float2*)(Ibase + (size_t)tt * BN);
                float rec[2] = {0.f, 0.f};
                if (prev_any) {
#pragma unroll 1
                    for (int w = 0; w < 16; ++w) {
                        unsigned m = smask[rb][w];
                        while (m) {
                            int bit = __ffs((int)m) - 1;
                            m &= (m - 1);
                            float2 wv = *(const float2*)(g_WT + ((size_t)(w * 32 + bit) << 9) + n0);
                            rec[0] += wv.x; rec[1] += wv.y;
                        }
                    }
                }
                const float Iin[2] = {It2.x, It2.y};
                float s[2];
                int spiked = 0;
#pragma unroll
                for (int k = 0; k < 2; ++k) {
                    rr[k] = rr[k] * e_syn + rec[k];
                    psc[k] = psc[k] * e_syn + KP * rr[k];
                    v[k] = v[k] + a_mem * (VR - v[k]) + a_mem * (Iin[k] + psc[k] + asc[k]);
                    bool inref = rcnt[k] > 0;
                    if (inref) v[k] = VR;
                    s[k] = (v[k] - VTH >= 0.0f) ? 1.0f : 0.0f;
                    if (s[k] > 0.0f) { v[k] = VR; rcnt[k] = 5; spiked = 1; }
                    else             { rcnt[k] = inref ? rcnt[k] - 1 : 0; }
                    asc[k] = asc[k] * e_asc + AA * s[k];
                    f[k] = (tt == 0) ? s[k] : (alpha * f[k] + oma * s[k]);
                    if (tt >= startT) fsum[k] += f[k];
                }
                if (writeHist) {
                    size_t idx = (size_t)tt * BN + (size_t)b * N_ + n0;
                    *(float2*)(vlt + idx)  = make_float2(v[0], v[1]);
                    *(float2*)(spk + idx)  = make_float2(s[0], s[1]);
                    *(float2*)(pscO + idx) = make_float2(psc[0], psc[1]);
                    *(float2*)(filt + idx) = make_float2(f[0], f[1]);
                }
                int any = __syncthreads_or(spiked);
                if (any && !s_ever) {
                    if (tid == 0) {
                        while (ldacq(&g_tp) < (unsigned)TP_BLKS) __nanosleep(64);
                        s_ever = 1;
                    }
                    __syncthreads();
                }
                if (any | prev_any) {
                    const int wb = rb ^ 1;
                    if (prev_any && tid < 16) smask[rb][tid] = 0u;
                    if (spiked) {
                        unsigned bits = 0u;
#pragma unroll
                        for (int k = 0; k < 2; ++k)
                            if (s[k] != 0.0f) bits |= 1u << (mbit0 + k);
                        atomicOr(&smask[wb][mword], bits);
                    }
                    __syncthreads();
                    if (any) rb = wb;
                }
                prev_any = any;
            }
        }

        // readout
        const float cnt = (float)(T - startT);
        const float osc = __ldg(osc_p);
        float a0 = (fsum[0] / cnt) * osc;
        float a1 = (fsum[1] / cnt) * osc;
#pragma unroll 1
        for (int o = 0; o < O_; ++o) {
            float2 w2 = *(const float2*)(Wout + (size_t)o * N_ + n0);
            float val = a0 * w2.x + a1 * w2.y;
#pragma unroll
            for (int off = 16; off > 0; off >>= 1)
                val += __shfl_down_sync(0xffffffffu, val, off);
            if (lane == 0) sred[wid] = val;
            __syncthreads();
            if (tid == 0) {
                float acc = __ldg(bout + o);
#pragma unroll
                for (int q = 0; q < 8; ++q) acc += sred[q];
                out[b * O_ + o] = acc;
            }
            __syncthreads();
        }
    }
}

extern "C" void kernel_launch(void* const* d_in, const int* in_sizes, int n_in,
                              void* d_out, int out_size) {
    const float* x    = (const float*)d_in[0];
    const float* Win  = (const float*)d_in[1];
    const float* isc  = (const float*)d_in[2];
    const float* Wrec = (const float*)d_in[3];
    const float* Wout = (const float*)d_in[4];
    const float* bout = (const float*)d_in[5];
    const float* osc  = (const float*)d_in[6];

    const int T = in_sizes[0] / (B_ * D_);
    float* out = (float*)d_out;
    const size_t TBN = (size_t)T * B_ * N_;
    const long long fullsz = (long long)B_ * O_ + 4LL * (long long)TBN;
    const int writeHist = ((long long)out_size >= fullsz) ? 1 : 0;
    float* spk = out + B_ * O_;
    float* vlt = spk + TBN;
    float* psc = vlt + TBN;
    float* flt = psc + TBN;

    const float e_syn = (float)exp((double)(-1.0f / 5.0f));
    const float e_asc = (float)exp((double)(-1.0f / 700.0f));
    const float alpha = (float)exp((double)(-1.0f / 20.0f));
    // int(T * (1.0 - 0.8)) truncates (float artifact): 199 for T=1000
    const int startT = (int)((double)T * (1.0 - 0.8));

    const int NG = (T / 2) * 4;                 // gemm CTAs (M-tiles x 4 N-tiles)
    const int grid = SIM_BLKS + NG + TP_BLKS;   // sim | gemm | transpose

    reset_kernel<<<1, 512>>>();

    cudaFuncSetAttribute(mega, cudaFuncAttributeMaxDynamicSharedMemorySize, GEMM_DSMEM);
    mega<<<grid, 256, GEMM_DSMEM>>>(x, Win, isc, Wrec, Wout, bout, osc,
                                    out, spk, vlt, psc, flt,
                                    T, startT, writeHist, e_syn, e_asc, alpha);
}